// round 1
// baseline (speedup 1.0000x reference)
#include <cuda_runtime.h>
#include <cstdint>

// ---------------------------------------------------------------------------
// QuantTrinaryFCMNIST: ternary 2-layer MLP with batch-stat BNs + TensorNorm.
//   h = tern(2x-1); C1 = h @ tern(W1)^T;           (int8 dp4a GEMM, exact int)
//   bn1 (batch stats, exact int sums) -> tern -> C2 = t @ tern(W2)^T
//   bn2 (batch stats) -> tern -> tensornorm (counts of {-1,0,1})
// All cross-batch statistics via integer atomics => deterministic.
// ---------------------------------------------------------------------------

#define B_ROWS 16384
#define K1     784
#define KP     800          // K1 padded to multiple of 32 (zero pad)
#define N1     1024
#define K2     1024
#define N2     10
#define OUT_N  (B_ROWS * N2)

typedef unsigned int uint;
typedef unsigned long long ull;

// ------------------------- scratch (device globals) ------------------------
__device__ int8_t g_Aq [B_ROWS * KP];          // ternarized input, padded
__device__ int8_t g_W1q[N1 * KP];              // ternarized W1, padded
__device__ int8_t g_W2q[N2 * K2];              // ternarized W2
__device__ int    g_C1 [B_ROWS * N1];          // exact int GEMM1 output
__device__ int    g_C2 [B_ROWS * N2];          // exact int GEMM2 output
__device__ int    g_sum1[N1];
__device__ ull    g_sq1 [N1];
__device__ float  g_scale1[N1], g_shift1[N1];
__device__ int    g_sum2[N2];
__device__ ull    g_sq2 [N2];
__device__ float  g_scale2[N2], g_shift2[N2];
__device__ int    g_cnt[2];                    // [0]=#(+1), [1]=#(-1)

__device__ __forceinline__ float ternf(float y) {
    // clamp(round-half-even(y), -1, 1) == jnp.clip(jnp.round(y), -1, 1)
    return fminf(1.f, fmaxf(-1.f, rintf(y)));
}

// ------------------------------ zero stats ---------------------------------
__global__ void zero_stats_kernel() {
    int t = threadIdx.x;
    if (t < N1) { g_sum1[t] = 0; g_sq1[t] = 0ull; }
    if (t < N2) { g_sum2[t] = 0; g_sq2[t] = 0ull; }
    if (t < 2)  { g_cnt[t] = 0; }
}

// --------------------------- quantize kernels ------------------------------
__global__ void quant_x_kernel(const float* __restrict__ x) {
    int idx = blockIdx.x * 256 + threadIdx.x;
    if (idx >= B_ROWS * KP) return;
    int row = idx / KP;
    int col = idx - row * KP;
    int8_t v = 0;
    if (col < K1) {
        float y = 2.0f * x[row * K1 + col] - 1.0f;
        v = (int8_t)(int)ternf(y);
    }
    g_Aq[idx] = v;
}

__global__ void quant_w1_kernel(const float* __restrict__ w) {
    int idx = blockIdx.x * 256 + threadIdx.x;
    if (idx >= N1 * KP) return;
    int row = idx / KP;
    int col = idx - row * KP;
    int8_t v = 0;
    if (col < K1) v = (int8_t)(int)ternf(w[row * K1 + col]);
    g_W1q[idx] = v;
}

__global__ void quant_w2_kernel(const float* __restrict__ w) {
    int idx = blockIdx.x * 256 + threadIdx.x;
    if (idx >= N2 * K2) return;
    g_W2q[idx] = (int8_t)(int)ternf(w[idx]);
}

// ------------------------------- GEMM1 --------------------------------------
// C1[16384,1024] = Aq[16384,KP] @ W1q[1024,KP]^T  (int8 x int8 -> int32, dp4a)
// Block tile 128x128, BK=32 bytes, 256 threads, 8x8 outputs/thread.
// Epilogue: exact per-column sum / sumsq accumulated for BN1 stats.
__global__ void __launch_bounds__(256)
gemm1_kernel() {
    __shared__ __align__(16) uint As[8][128];   // [k-group][m-row], 4 k-bytes/word
    __shared__ __align__(16) uint Bs[8][128];   // [k-group][n-row]
    __shared__ int s_sum[128];
    __shared__ int s_sq [128];

    const int t    = threadIdx.x;
    const int am0  = blockIdx.x * 128;
    const int bn0  = blockIdx.y * 128;
    const int lrow = t >> 1;       // 0..127
    const int lseg = t & 1;        // 0..1 (16B halves of 32B k-slab)
    const int ty   = t >> 4;       // 0..15
    const int tx   = t & 15;       // 0..15

    int acc[8][8];
#pragma unroll
    for (int i = 0; i < 8; i++)
#pragma unroll
        for (int j = 0; j < 8; j++) acc[i][j] = 0;

    const int8_t* Ag = g_Aq  + (size_t)(am0 + lrow) * KP + lseg * 16;
    const int8_t* Bg = g_W1q + (size_t)(bn0 + lrow) * KP + lseg * 16;

    for (int kb = 0; kb < KP; kb += 32) {
        uint4 av = *reinterpret_cast<const uint4*>(Ag + kb);
        uint4 bv = *reinterpret_cast<const uint4*>(Bg + kb);
        As[lseg * 4 + 0][lrow] = av.x;
        As[lseg * 4 + 1][lrow] = av.y;
        As[lseg * 4 + 2][lrow] = av.z;
        As[lseg * 4 + 3][lrow] = av.w;
        Bs[lseg * 4 + 0][lrow] = bv.x;
        Bs[lseg * 4 + 1][lrow] = bv.y;
        Bs[lseg * 4 + 2][lrow] = bv.z;
        Bs[lseg * 4 + 3][lrow] = bv.w;
        __syncthreads();

#pragma unroll
        for (int kk = 0; kk < 8; kk++) {
            uint4 a0 = *reinterpret_cast<const uint4*>(&As[kk][ty * 8]);
            uint4 a1 = *reinterpret_cast<const uint4*>(&As[kk][ty * 8 + 4]);
            uint4 b0 = *reinterpret_cast<const uint4*>(&Bs[kk][tx * 8]);
            uint4 b1 = *reinterpret_cast<const uint4*>(&Bs[kk][tx * 8 + 4]);
            int a[8] = {(int)a0.x, (int)a0.y, (int)a0.z, (int)a0.w,
                        (int)a1.x, (int)a1.y, (int)a1.z, (int)a1.w};
            int b[8] = {(int)b0.x, (int)b0.y, (int)b0.z, (int)b0.w,
                        (int)b1.x, (int)b1.y, (int)b1.z, (int)b1.w};
#pragma unroll
            for (int i = 0; i < 8; i++)
#pragma unroll
                for (int j = 0; j < 8; j++)
                    acc[i][j] = __dp4a(a[i], b[j], acc[i][j]);
        }
        __syncthreads();
    }

    // write C1 tile
#pragma unroll
    for (int i = 0; i < 8; i++) {
        int4* p = reinterpret_cast<int4*>(
            g_C1 + (size_t)(am0 + ty * 8 + i) * N1 + bn0 + tx * 8);
        p[0] = make_int4(acc[i][0], acc[i][1], acc[i][2], acc[i][3]);
        p[1] = make_int4(acc[i][4], acc[i][5], acc[i][6], acc[i][7]);
    }

    // per-column partial sums over this block's 128 rows (exact int)
    int csum[8], csq[8];
#pragma unroll
    for (int j = 0; j < 8; j++) { csum[j] = 0; csq[j] = 0; }
#pragma unroll
    for (int i = 0; i < 8; i++)
#pragma unroll
        for (int j = 0; j < 8; j++) {
            csum[j] += acc[i][j];
            csq[j]  += acc[i][j] * acc[i][j];   // <= 8*784^2 < 2^31
        }

    if (t < 128) { s_sum[t] = 0; s_sq[t] = 0; }
    __syncthreads();
#pragma unroll
    for (int j = 0; j < 8; j++) {
        atomicAdd(&s_sum[tx * 8 + j], csum[j]);
        atomicAdd(&s_sq [tx * 8 + j], csq[j]);   // <= 128*784^2 < 2^31
    }
    __syncthreads();
    if (t < 128) {
        atomicAdd(&g_sum1[bn0 + t], s_sum[t]);
        atomicAdd(&g_sq1 [bn0 + t], (ull)(uint)s_sq[t]);
    }
}

// -------------------------- BN param kernels --------------------------------
__global__ void bn1_params_kernel(const float* __restrict__ gamma,
                                  const float* __restrict__ beta) {
    int j = blockIdx.x * 256 + threadIdx.x;
    if (j >= N1) return;
    double mean = (double)g_sum1[j] * (1.0 / 16384.0);
    double var  = (double)g_sq1[j]  * (1.0 / 16384.0) - mean * mean; // biased
    float  sc   = gamma[j] * (float)(1.0 / sqrt(var + 1e-5));
    g_scale1[j] = sc;
    g_shift1[j] = beta[j] - (float)mean * sc;
}

__global__ void bn2_params_kernel(const float* __restrict__ gamma,
                                  const float* __restrict__ beta) {
    int j = threadIdx.x;
    if (j >= N2) return;
    double mean = (double)g_sum2[j] * (1.0 / 16384.0);
    double var  = (double)g_sq2[j]  * (1.0 / 16384.0) - mean * mean;
    float  sc   = gamma[j] * (float)(1.0 / sqrt(var + 1e-5));
    g_scale2[j] = sc;
    g_shift2[j] = beta[j] - (float)mean * sc;
}

// ------------------------------- GEMM2 --------------------------------------
// Fused: t = tern(bn1(C1)); C2[16384,10] = t @ W2q^T; exact BN2 stats.
// One warp per row; 8 rows per block.
__global__ void __launch_bounds__(256)
gemm2_kernel() {
    __shared__ uint  w2p[N2 * 256];          // W2 packed 4 int8 / uint, [j][k4]
    __shared__ float ss[K2], sh[K2];
    __shared__ int   bsum[N2], bsq[N2];

    const int t = threadIdx.x;
    for (int i = t; i < N2 * 256; i += 256)
        w2p[i] = reinterpret_cast<const uint*>(g_W2q)[i];
    for (int i = t; i < K2; i += 256) { ss[i] = g_scale1[i]; sh[i] = g_shift1[i]; }
    if (t < N2) { bsum[t] = 0; bsq[t] = 0; }
    __syncthreads();

    const int warp = t >> 5, lane = t & 31;
    const int row  = blockIdx.x * 8 + warp;

    int acc[N2];
#pragma unroll
    for (int j = 0; j < N2; j++) acc[j] = 0;

#pragma unroll
    for (int it = 0; it < 8; it++) {
        int  k4 = it * 32 + lane;                 // uint index 0..255
        int4 c  = *reinterpret_cast<const int4*>(g_C1 + (size_t)row * K2 + k4 * 4);
        float4 sc = *reinterpret_cast<const float4*>(&ss[k4 * 4]);
        float4 sf = *reinterpret_cast<const float4*>(&sh[k4 * 4]);
        int t0 = (int)ternf((float)c.x * sc.x + sf.x);
        int t1 = (int)ternf((float)c.y * sc.y + sf.y);
        int t2 = (int)ternf((float)c.z * sc.z + sf.z);
        int t3 = (int)ternf((float)c.w * sc.w + sf.w);
        uint packed = (uint)(t0 & 0xff) | ((uint)(t1 & 0xff) << 8) |
                      ((uint)(t2 & 0xff) << 16) | ((uint)(t3 & 0xff) << 24);
#pragma unroll
        for (int j = 0; j < N2; j++)
            acc[j] = __dp4a((int)packed, (int)w2p[j * 256 + k4], acc[j]);
    }

    // warp butterfly reduce (every lane ends with full row sums)
#pragma unroll
    for (int j = 0; j < N2; j++)
#pragma unroll
        for (int o = 16; o > 0; o >>= 1)
            acc[j] += __shfl_xor_sync(0xffffffffu, acc[j], o);

    if (lane < N2) {
        int v = acc[lane];
        g_C2[row * N2 + lane] = v;
        atomicAdd(&bsum[lane], v);
        atomicAdd(&bsq [lane], v * v);           // <= 8*1024^2 < 2^31
    }
    __syncthreads();
    if (t < N2) {
        atomicAdd(&g_sum2[t], bsum[t]);
        atomicAdd(&g_sq2 [t], (ull)(uint)bsq[t]);
    }
}

// ------------------- ternary counts for TensorNorm --------------------------
__global__ void count_kernel() {
    int idx = blockIdx.x * 256 + threadIdx.x;
    int pos = 0, neg = 0;
    if (idx < OUT_N) {
        int j = idx % N2;
        float y = (float)g_C2[idx] * g_scale2[j] + g_shift2[j];
        float tv = ternf(y);
        pos = tv > 0.5f;
        neg = tv < -0.5f;
    }
#pragma unroll
    for (int o = 16; o > 0; o >>= 1) {
        pos += __shfl_xor_sync(0xffffffffu, pos, o);
        neg += __shfl_xor_sync(0xffffffffu, neg, o);
    }
    __shared__ int s[2];
    if (threadIdx.x == 0) { s[0] = 0; s[1] = 0; }
    __syncthreads();
    if ((threadIdx.x & 31) == 0) { atomicAdd(&s[0], pos); atomicAdd(&s[1], neg); }
    __syncthreads();
    if (threadIdx.x == 0) { atomicAdd(&g_cnt[0], s[0]); atomicAdd(&g_cnt[1], s[1]); }
}

// ------------------------------ final output --------------------------------
__global__ void final_kernel(const float* __restrict__ tn_w,
                             const float* __restrict__ tn_b,
                             float* __restrict__ out) {
    int idx = blockIdx.x * 256 + threadIdx.x;
    if (idx >= OUT_N) return;
    int j = idx % N2;
    float y  = (float)g_C2[idx] * g_scale2[j] + g_shift2[j];
    float tv = ternf(y);

    const double N  = (double)OUT_N;
    double np = (double)g_cnt[0], nn = (double)g_cnt[1];
    double mean = (np - nn) / N;
    double ssq  = np + nn;                      // sum of t^2 (t in {-1,0,1})
    double var  = (ssq - N * mean * mean) / (N - 1.0);   // ddof=1
    float  inv  = (float)(1.0 / sqrt(var + 1e-4));

    out[idx] = (tv - (float)mean) * inv * tn_w[0] + tn_b[0];
}

// ------------------------------ launcher ------------------------------------
extern "C" void kernel_launch(void* const* d_in, const int* in_sizes, int n_in,
                              void* d_out, int out_size) {
    const float* x      = (const float*)d_in[0];
    const float* W1     = (const float*)d_in[1];
    const float* gamma1 = (const float*)d_in[2];
    const float* beta1  = (const float*)d_in[3];
    const float* W2     = (const float*)d_in[4];
    const float* gamma2 = (const float*)d_in[5];
    const float* beta2  = (const float*)d_in[6];
    const float* tn_w   = (const float*)d_in[7];
    const float* tn_b   = (const float*)d_in[8];
    float* out = (float*)d_out;

    zero_stats_kernel<<<1, 1024>>>();
    quant_x_kernel <<<(B_ROWS * KP + 255) / 256, 256>>>(x);
    quant_w1_kernel<<<(N1 * KP + 255) / 256, 256>>>(W1);
    quant_w2_kernel<<<(N2 * K2 + 255) / 256, 256>>>(W2);

    dim3 g1(B_ROWS / 128, N1 / 128);
    gemm1_kernel<<<g1, 256>>>();
    bn1_params_kernel<<<(N1 + 255) / 256, 256>>>(gamma1, beta1);

    gemm2_kernel<<<B_ROWS / 8, 256>>>();
    bn2_params_kernel<<<1, 32>>>(gamma2, beta2);

    count_kernel<<<OUT_N / 256, 256>>>();
    final_kernel<<<OUT_N / 256, 256>>>(tn_w, tn_b, out);
}

// round 3
// speedup vs baseline: 1.0354x; 1.0354x over previous
#include <cuda_runtime.h>
#include <cstdint>

// ---------------------------------------------------------------------------
// QuantTrinaryFCMNIST — Round 3: GEMM1 via baseline-PTX mma.sync IMMA
// (tcgen05 rejected: harness compiles through compute_103 base target).
// Ternary {-1,0,1} in int8; s8 MMA exact; BN stats exact int atomics.
// ---------------------------------------------------------------------------

#define B_ROWS 16384
#define K1     784
#define KP     832          // padded to 13 chunks of 64
#define NCH    13
#define N1     1024
#define K2     1024
#define N2     10
#define OUT_N  (B_ROWS * N2)

typedef unsigned int uint;
typedef unsigned long long ull;

// ------------------------- scratch (device globals) ------------------------
__device__ int8_t g_Aq [(size_t)B_ROWS * KP];
__device__ int8_t g_W1q[(size_t)N1 * KP];
__device__ int8_t g_W2q[N2 * K2];
__device__ int    g_C1 [(size_t)B_ROWS * N1];
__device__ int    g_C2 [OUT_N];
__device__ int    g_sum1[N1];
__device__ ull    g_sq1 [N1];
__device__ float  g_scale1[N1], g_shift1[N1];
__device__ int    g_sum2[N2];
__device__ ull    g_sq2 [N2];
__device__ float  g_scale2[N2], g_shift2[N2];
__device__ int    g_cnt[2];

__device__ __forceinline__ float ternf(float y) {
    return fminf(1.f, fmaxf(-1.f, rintf(y)));   // == jnp.clip(jnp.round(y),-1,1)
}

// ------------------------------ zero stats ---------------------------------
__global__ void zero_stats_kernel() {
    int t = threadIdx.x;
    if (t < N1) { g_sum1[t] = 0; g_sq1[t] = 0ull; }
    if (t < N2) { g_sum2[t] = 0; g_sq2[t] = 0ull; }
    if (t < 2)  { g_cnt[t] = 0; }
}

// --------------------------- quantize kernels ------------------------------
__global__ void quant_x_kernel(const float* __restrict__ x) {
    int idx = blockIdx.x * 256 + threadIdx.x;
    if (idx >= B_ROWS * KP) return;
    int row = idx / KP;
    int col = idx - row * KP;
    int8_t v = 0;
    if (col < K1) v = (int8_t)(int)ternf(2.0f * x[row * K1 + col] - 1.0f);
    g_Aq[idx] = v;
}

__global__ void quant_w1_kernel(const float* __restrict__ w) {
    int idx = blockIdx.x * 256 + threadIdx.x;
    if (idx >= N1 * KP) return;
    int row = idx / KP;
    int col = idx - row * KP;
    int8_t v = 0;
    if (col < K1) v = (int8_t)(int)ternf(w[row * K1 + col]);
    g_W1q[idx] = v;
}

__global__ void quant_w2_kernel(const float* __restrict__ w) {
    int idx = blockIdx.x * 256 + threadIdx.x;
    if (idx >= N2 * K2) return;
    g_W2q[idx] = (int8_t)(int)ternf(w[idx]);
}

// ------------------------------- GEMM1 (IMMA) -------------------------------
// C1[16384,1024] = Aq @ W1q^T. Tile 128x128, BK=64, 8 warps (4x2),
// each warp 32x64 via mma.sync.m16n8k32.s8. Fused exact BN1 stats.
#define SROW 80   // smem row stride (bytes): conflict-free for frag pattern

__device__ __forceinline__ void imma16832(int* d, const int* a, const int* b) {
    asm volatile(
        "mma.sync.aligned.m16n8k32.row.col.s32.s8.s8.s32 "
        "{%0,%1,%2,%3}, {%4,%5,%6,%7}, {%8,%9}, {%0,%1,%2,%3};"
        : "+r"(d[0]), "+r"(d[1]), "+r"(d[2]), "+r"(d[3])
        : "r"(a[0]), "r"(a[1]), "r"(a[2]), "r"(a[3]), "r"(b[0]), "r"(b[1]));
}

__global__ void __launch_bounds__(256)
gemm1_kernel() {
    __shared__ __align__(16) char sA[2][128 * SROW];
    __shared__ __align__(16) char sB[2][128 * SROW];
    __shared__ int s_sum[128];
    __shared__ int s_sq [128];

    const int t = threadIdx.x;
    const int wid = t >> 5, lane = t & 31;
    const int warp_m = wid & 3, warp_n = wid >> 2;
    const int m0 = blockIdx.x * 128;
    const int n0 = blockIdx.y * 128;

    int acc[2][8][4];
#pragma unroll
    for (int mi = 0; mi < 2; mi++)
#pragma unroll
        for (int ni = 0; ni < 8; ni++)
#pragma unroll
            for (int k = 0; k < 4; k++) acc[mi][ni][k] = 0;

    // loader: thread t owns rows r0 and r0+64, 16B segment s0, for A and B
    const int r0 = t >> 2, s0 = t & 3;
    const int8_t* Ag0 = g_Aq  + (size_t)(m0 + r0)      * KP + s0 * 16;
    const int8_t* Ag1 = g_Aq  + (size_t)(m0 + r0 + 64) * KP + s0 * 16;
    const int8_t* Bg0 = g_W1q + (size_t)(n0 + r0)      * KP + s0 * 16;
    const int8_t* Bg1 = g_W1q + (size_t)(n0 + r0 + 64) * KP + s0 * 16;

    uint4 ra0, ra1, rb0, rb1;
    // prefetch + store chunk 0 into buf 0
    ra0 = *reinterpret_cast<const uint4*>(Ag0);
    ra1 = *reinterpret_cast<const uint4*>(Ag1);
    rb0 = *reinterpret_cast<const uint4*>(Bg0);
    rb1 = *reinterpret_cast<const uint4*>(Bg1);
    *reinterpret_cast<uint4*>(&sA[0][0] + r0 * SROW + s0 * 16)        = ra0;
    *reinterpret_cast<uint4*>(&sA[0][0] + (r0 + 64) * SROW + s0 * 16) = ra1;
    *reinterpret_cast<uint4*>(&sB[0][0] + r0 * SROW + s0 * 16)        = rb0;
    *reinterpret_cast<uint4*>(&sB[0][0] + (r0 + 64) * SROW + s0 * 16) = rb1;
    __syncthreads();

    const int frow = lane >> 2;              // 0..7
    const int fcol = (lane & 3) * 4;         // 0,4,8,12

    for (int kc = 0; kc < NCH; kc++) {
        const int buf = kc & 1;
        if (kc + 1 < NCH) {
            ra0 = *reinterpret_cast<const uint4*>(Ag0 + (kc + 1) * 64);
            ra1 = *reinterpret_cast<const uint4*>(Ag1 + (kc + 1) * 64);
            rb0 = *reinterpret_cast<const uint4*>(Bg0 + (kc + 1) * 64);
            rb1 = *reinterpret_cast<const uint4*>(Bg1 + (kc + 1) * 64);
        }

        const char* cA = &sA[buf][0];
        const char* cB = &sB[buf][0];
#pragma unroll
        for (int ks = 0; ks < 2; ks++) {
            const int kb = ks * 32 + fcol;
            int a[2][4], b[8][2];
#pragma unroll
            for (int mi = 0; mi < 2; mi++) {
                const char* p = cA + (warp_m * 32 + mi * 16 + frow) * SROW + kb;
                a[mi][0] = *reinterpret_cast<const int*>(p);
                a[mi][1] = *reinterpret_cast<const int*>(p + 8 * SROW);
                a[mi][2] = *reinterpret_cast<const int*>(p + 16);
                a[mi][3] = *reinterpret_cast<const int*>(p + 8 * SROW + 16);
            }
#pragma unroll
            for (int ni = 0; ni < 8; ni++) {
                const char* p = cB + (warp_n * 64 + ni * 8 + frow) * SROW + kb;
                b[ni][0] = *reinterpret_cast<const int*>(p);
                b[ni][1] = *reinterpret_cast<const int*>(p + 16);
            }
#pragma unroll
            for (int mi = 0; mi < 2; mi++)
#pragma unroll
                for (int ni = 0; ni < 8; ni++)
                    imma16832(acc[mi][ni], a[mi], b[ni]);
        }
        __syncthreads();
        if (kc + 1 < NCH) {
            const int nb = (kc + 1) & 1;
            *reinterpret_cast<uint4*>(&sA[nb][0] + r0 * SROW + s0 * 16)        = ra0;
            *reinterpret_cast<uint4*>(&sA[nb][0] + (r0 + 64) * SROW + s0 * 16) = ra1;
            *reinterpret_cast<uint4*>(&sB[nb][0] + r0 * SROW + s0 * 16)        = rb0;
            *reinterpret_cast<uint4*>(&sB[nb][0] + (r0 + 64) * SROW + s0 * 16) = rb1;
            __syncthreads();
        }
    }

    // ------------- write C1 + fused exact BN1 stats -------------
    const int crow = warp_m * 32 + frow;          // local row of c0/c1
    const int ccol = warp_n * 64 + (lane & 3) * 2;
#pragma unroll
    for (int mi = 0; mi < 2; mi++)
#pragma unroll
        for (int ni = 0; ni < 8; ni++) {
            int r = m0 + crow + mi * 16;
            int c = n0 + ccol + ni * 8;
            *reinterpret_cast<int2*>(g_C1 + (size_t)r * N1 + c) =
                make_int2(acc[mi][ni][0], acc[mi][ni][1]);
            *reinterpret_cast<int2*>(g_C1 + (size_t)(r + 8) * N1 + c) =
                make_int2(acc[mi][ni][2], acc[mi][ni][3]);
        }

    if (t < 128) { s_sum[t] = 0; s_sq[t] = 0; }
    __syncthreads();
#pragma unroll
    for (int ni = 0; ni < 8; ni++) {
#pragma unroll
        for (int p = 0; p < 2; p++) {
            int v0 = acc[0][ni][p],     v1 = acc[0][ni][p + 2];
            int v2 = acc[1][ni][p],     v3 = acc[1][ni][p + 2];
            int s = v0 + v1 + v2 + v3;
            int q = v0 * v0 + v1 * v1 + v2 * v2 + v3 * v3;  // <= 4*784^2
            int col = ccol + ni * 8 + p;
            atomicAdd(&s_sum[col], s);
            atomicAdd(&s_sq [col], q);    // <= 128*784^2 < 2^31
        }
    }
    __syncthreads();
    if (t < 128) {
        atomicAdd(&g_sum1[n0 + t], s_sum[t]);
        atomicAdd(&g_sq1 [n0 + t], (ull)(uint)s_sq[t]);
    }
}

// -------------------------- BN param kernels --------------------------------
__global__ void bn1_params_kernel(const float* __restrict__ gamma,
                                  const float* __restrict__ beta) {
    int j = blockIdx.x * 256 + threadIdx.x;
    if (j >= N1) return;
    double mean = (double)g_sum1[j] * (1.0 / 16384.0);
    double var  = (double)g_sq1[j]  * (1.0 / 16384.0) - mean * mean;
    float  sc   = gamma[j] * (float)(1.0 / sqrt(var + 1e-5));
    g_scale1[j] = sc;
    g_shift1[j] = beta[j] - (float)mean * sc;
}

__global__ void bn2_params_kernel(const float* __restrict__ gamma,
                                  const float* __restrict__ beta) {
    int j = threadIdx.x;
    if (j >= N2) return;
    double mean = (double)g_sum2[j] * (1.0 / 16384.0);
    double var  = (double)g_sq2[j]  * (1.0 / 16384.0) - mean * mean;
    float  sc   = gamma[j] * (float)(1.0 / sqrt(var + 1e-5));
    g_scale2[j] = sc;
    g_shift2[j] = beta[j] - (float)mean * sc;
}

// ------------------------------- GEMM2 --------------------------------------
__global__ void __launch_bounds__(256)
gemm2_kernel() {
    __shared__ uint  w2p[N2 * 256];
    __shared__ float ss[K2], sh[K2];
    __shared__ int   bsum[N2], bsq[N2];

    const int t = threadIdx.x;
    for (int i = t; i < N2 * 256; i += 256)
        w2p[i] = reinterpret_cast<const uint*>(g_W2q)[i];
    for (int i = t; i < K2; i += 256) { ss[i] = g_scale1[i]; sh[i] = g_shift1[i]; }
    if (t < N2) { bsum[t] = 0; bsq[t] = 0; }
    __syncthreads();

    const int warp = t >> 5, lane = t & 31;
    const int row  = blockIdx.x * 8 + warp;

    int acc[N2];
#pragma unroll
    for (int j = 0; j < N2; j++) acc[j] = 0;

#pragma unroll
    for (int it = 0; it < 8; it++) {
        int  k4 = it * 32 + lane;
        int4 c  = *reinterpret_cast<const int4*>(g_C1 + (size_t)row * K2 + k4 * 4);
        float4 sc = *reinterpret_cast<const float4*>(&ss[k4 * 4]);
        float4 sf = *reinterpret_cast<const float4*>(&sh[k4 * 4]);
        int t0 = (int)ternf((float)c.x * sc.x + sf.x);
        int t1 = (int)ternf((float)c.y * sc.y + sf.y);
        int t2 = (int)ternf((float)c.z * sc.z + sf.z);
        int t3 = (int)ternf((float)c.w * sc.w + sf.w);
        uint packed = (uint)(t0 & 0xff) | ((uint)(t1 & 0xff) << 8) |
                      ((uint)(t2 & 0xff) << 16) | ((uint)(t3 & 0xff) << 24);
#pragma unroll
        for (int j = 0; j < N2; j++)
            acc[j] = __dp4a((int)packed, (int)w2p[j * 256 + k4], acc[j]);
    }

#pragma unroll
    for (int j = 0; j < N2; j++)
#pragma unroll
        for (int o = 16; o > 0; o >>= 1)
            acc[j] += __shfl_xor_sync(0xffffffffu, acc[j], o);

    if (lane < N2) {
        int v = acc[lane];
        g_C2[row * N2 + lane] = v;
        atomicAdd(&bsum[lane], v);
        atomicAdd(&bsq [lane], v * v);
    }
    __syncthreads();
    if (t < N2) {
        atomicAdd(&g_sum2[t], bsum[t]);
        atomicAdd(&g_sq2 [t], (ull)(uint)bsq[t]);
    }
}

// ------------------- ternary counts for TensorNorm --------------------------
__global__ void count_kernel() {
    int idx = blockIdx.x * 256 + threadIdx.x;
    int pos = 0, neg = 0;
    if (idx < OUT_N) {
        int j = idx % N2;
        float y = (float)g_C2[idx] * g_scale2[j] + g_shift2[j];
        float tv = ternf(y);
        pos = tv > 0.5f;
        neg = tv < -0.5f;
    }
#pragma unroll
    for (int o = 16; o > 0; o >>= 1) {
        pos += __shfl_xor_sync(0xffffffffu, pos, o);
        neg += __shfl_xor_sync(0xffffffffu, neg, o);
    }
    __shared__ int s[2];
    if (threadIdx.x == 0) { s[0] = 0; s[1] = 0; }
    __syncthreads();
    if ((threadIdx.x & 31) == 0) { atomicAdd(&s[0], pos); atomicAdd(&s[1], neg); }
    __syncthreads();
    if (threadIdx.x == 0) { atomicAdd(&g_cnt[0], s[0]); atomicAdd(&g_cnt[1], s[1]); }
}

// ------------------------------ final output --------------------------------
__global__ void final_kernel(const float* __restrict__ tn_w,
                             const float* __restrict__ tn_b,
                             float* __restrict__ out) {
    int idx = blockIdx.x * 256 + threadIdx.x;
    if (idx >= OUT_N) return;
    int j = idx % N2;
    float y  = (float)g_C2[idx] * g_scale2[j] + g_shift2[j];
    float tv = ternf(y);

    const double N = (double)OUT_N;
    double np = (double)g_cnt[0], nn = (double)g_cnt[1];
    double mean = (np - nn) / N;
    double ssq  = np + nn;
    double var  = (ssq - N * mean * mean) / (N - 1.0);
    float  inv  = (float)(1.0 / sqrt(var + 1e-4));

    out[idx] = (tv - (float)mean) * inv * tn_w[0] + tn_b[0];
}

// ------------------------------ launcher ------------------------------------
extern "C" void kernel_launch(void* const* d_in, const int* in_sizes, int n_in,
                              void* d_out, int out_size) {
    const float* x      = (const float*)d_in[0];
    const float* W1     = (const float*)d_in[1];
    const float* gamma1 = (const float*)d_in[2];
    const float* beta1  = (const float*)d_in[3];
    const float* W2     = (const float*)d_in[4];
    const float* gamma2 = (const float*)d_in[5];
    const float* beta2  = (const float*)d_in[6];
    const float* tn_w   = (const float*)d_in[7];
    const float* tn_b   = (const float*)d_in[8];
    float* out = (float*)d_out;

    zero_stats_kernel<<<1, 1024>>>();
    quant_x_kernel <<<(B_ROWS * KP + 255) / 256, 256>>>(x);
    quant_w1_kernel<<<(N1 * KP + 255) / 256, 256>>>(W1);
    quant_w2_kernel<<<(N2 * K2 + 255) / 256, 256>>>(W2);

    dim3 g1(B_ROWS / 128, N1 / 128);
    gemm1_kernel<<<g1, 256>>>();
    bn1_params_kernel<<<(N1 + 255) / 256, 256>>>(gamma1, beta1);

    gemm2_kernel<<<B_ROWS / 8, 256>>>();
    bn2_params_kernel<<<1, 32>>>(gamma2, beta2);

    count_kernel<<<OUT_N / 256, 256>>>();
    final_kernel<<<OUT_N / 256, 256>>>(tn_w, tn_b, out);
}